// round 1
// baseline (speedup 1.0000x reference)
#include <cuda_runtime.h>
#include <cstdint>

// Chamfer distance, B=8, D=3, N=4096, fp32.
// P[b,i,j] = |s_i|^2 + |t_j|^2 - 2 s_i.t_j
// loss = mean_j min_i P + mean_i min_j P
//
// Strategy: compute-bound kernel using packed fma.rn.f32x2 (2 target columns
// per instruction), 2 source rows per lane (64 rows/warp), running FMNMX for
// row mins and redux.sync.min.u32 + global atomicMin (u32 bit-pattern, values
// are nonneg d^2) for column mins. Targets staged in SMEM SoA per block.

#define B_ 8
#define N_ 4096
#define ROWTILE 256      // rows per block = 4 warps * 64 rows
#define COLTILE 1024     // target columns per block
#define THREADS 128

__device__ unsigned g_rowmin[B_ * N_];   // min over targets, per source (u32 fp bits)
__device__ unsigned g_colmin[B_ * N_];   // min over sources, per target

typedef unsigned long long u64;

__device__ __forceinline__ u64 pack2(float a, float b) {
    u64 r; asm("mov.b64 %0,{%1,%2};" : "=l"(r) : "f"(a), "f"(b)); return r;
}
__device__ __forceinline__ void unpack2(u64 v, float& a, float& b) {
    asm("mov.b64 {%0,%1},%2;" : "=f"(a), "=f"(b) : "l"(v));
}
__device__ __forceinline__ u64 add2(u64 a, u64 b) {
    u64 r; asm("add.rn.f32x2 %0,%1,%2;" : "=l"(r) : "l"(a), "l"(b)); return r;
}
__device__ __forceinline__ u64 fma2(u64 a, u64 b, u64 c) {
    u64 r; asm("fma.rn.f32x2 %0,%1,%2,%3;" : "=l"(r) : "l"(a), "l"(b), "l"(c)); return r;
}
__device__ __forceinline__ unsigned redux_min_u32(unsigned v) {
    unsigned r; asm("redux.sync.min.u32 %0,%1,0xffffffff;" : "=r"(r) : "r"(v)); return r;
}

__global__ void cd_init_kernel() {
    int i = blockIdx.x * blockDim.x + threadIdx.x;
    if (i < B_ * N_) {
        g_rowmin[i] = 0x7F800000u;  // +inf
        g_colmin[i] = 0x7F800000u;
    }
}

__global__ __launch_bounds__(THREADS) void cd_main_kernel(
    const float* __restrict__ srcs, const float* __restrict__ tgts) {
    __shared__ __align__(16) float smx[COLTILE];
    __shared__ __align__(16) float smy[COLTILE];
    __shared__ __align__(16) float smz[COLTILE];
    __shared__ __align__(16) float smr[COLTILE];

    const int b    = blockIdx.z;
    const int row0 = blockIdx.y * ROWTILE;
    const int c0   = blockIdx.x * COLTILE;

    // Stage target tile (SoA: x, y, z, |t|^2)
    const float* tb = tgts + (size_t)b * 3 * N_;
    for (int j = threadIdx.x; j < COLTILE; j += THREADS) {
        float x = tb[c0 + j];
        float y = tb[N_ + c0 + j];
        float z = tb[2 * N_ + c0 + j];
        smx[j] = x; smy[j] = y; smz[j] = z;
        smr[j] = x * x + y * y + z * z;
    }
    __syncthreads();

    const int w    = threadIdx.x >> 5;
    const int lane = threadIdx.x & 31;
    const int iA   = row0 + w * 64 + lane;
    const int iB   = iA + 32;

    const float* sb = srcs + (size_t)b * 3 * N_;
    const float axA = sb[iA], ayA = sb[N_ + iA], azA = sb[2 * N_ + iA];
    const float axB = sb[iB], ayB = sb[N_ + iB], azB = sb[2 * N_ + iB];
    const float rsA = axA * axA + ayA * ayA + azA * azA;
    const float rsB = axB * axB + ayB * ayB + azB * azB;

    const u64 nxA = pack2(-2.f * axA, -2.f * axA);
    const u64 nyA = pack2(-2.f * ayA, -2.f * ayA);
    const u64 nzA = pack2(-2.f * azA, -2.f * azA);
    const u64 nxB = pack2(-2.f * axB, -2.f * axB);
    const u64 nyB = pack2(-2.f * ayB, -2.f * ayB);
    const u64 nzB = pack2(-2.f * azB, -2.f * azB);
    const u64 rsA2 = pack2(rsA, rsA);
    const u64 rsB2 = pack2(rsB, rsB);

    const float INF = __int_as_float(0x7F800000);
    float rA0 = INF, rA1 = INF, rA2_ = INF, rA3 = INF;
    float rB0 = INF, rB1 = INF, rB2_ = INF, rB3 = INF;

    #pragma unroll 4
    for (int j = 0; j < COLTILE; j += 4) {
        const ulonglong2 Xv = *reinterpret_cast<const ulonglong2*>(smx + j);
        const ulonglong2 Yv = *reinterpret_cast<const ulonglong2*>(smy + j);
        const ulonglong2 Zv = *reinterpret_cast<const ulonglong2*>(smz + j);
        const ulonglong2 Rv = *reinterpret_cast<const ulonglong2*>(smr + j);

        // columns j, j+1
        u64 aA = fma2(nzA, Zv.x, fma2(nyA, Yv.x, fma2(nxA, Xv.x, add2(rsA2, Rv.x))));
        u64 aB = fma2(nzB, Zv.x, fma2(nyB, Yv.x, fma2(nxB, Xv.x, add2(rsB2, Rv.x))));
        float a0, a1, b0, b1;
        unpack2(aA, a0, a1); unpack2(aB, b0, b1);
        rA0 = fminf(rA0, a0); rA1 = fminf(rA1, a1);
        rB0 = fminf(rB0, b0); rB1 = fminf(rB1, b1);
        const unsigned u0 = redux_min_u32(__float_as_uint(fminf(a0, b0)));
        const unsigned u1 = redux_min_u32(__float_as_uint(fminf(a1, b1)));

        // columns j+2, j+3
        u64 cA = fma2(nzA, Zv.y, fma2(nyA, Yv.y, fma2(nxA, Xv.y, add2(rsA2, Rv.y))));
        u64 cB = fma2(nzB, Zv.y, fma2(nyB, Yv.y, fma2(nxB, Xv.y, add2(rsB2, Rv.y))));
        float c0v, c1v, d0v, d1v;
        unpack2(cA, c0v, c1v); unpack2(cB, d0v, d1v);
        rA2_ = fminf(rA2_, c0v); rA3 = fminf(rA3, c1v);
        rB2_ = fminf(rB2_, d0v); rB3 = fminf(rB3, d1v);
        const unsigned u2 = redux_min_u32(__float_as_uint(fminf(c0v, d0v)));
        const unsigned u3 = redux_min_u32(__float_as_uint(fminf(c1v, d1v)));

        if (lane < 4) {
            unsigned v = (lane & 1) ? ((lane & 2) ? u3 : u1)
                                    : ((lane & 2) ? u2 : u0);
            atomicMin(&g_colmin[b * N_ + c0 + j + lane], v);
        }
    }

    float rowA = fmaxf(fminf(fminf(rA0, rA1), fminf(rA2_, rA3)), 0.f);
    float rowB = fmaxf(fminf(fminf(rB0, rB1), fminf(rB2_, rB3)), 0.f);
    atomicMin(&g_rowmin[b * N_ + iA], __float_as_uint(rowA));
    atomicMin(&g_rowmin[b * N_ + iB], __float_as_uint(rowB));
}

__global__ void cd_reduce_kernel(float* __restrict__ out) {
    __shared__ double sdata[32];
    const int tid = threadIdx.x;  // 1024 threads
    double s = 0.0;
    for (int i = tid; i < B_ * N_; i += 1024) {
        s += (double)__uint_as_float(g_rowmin[i]);
        s += (double)__uint_as_float(g_colmin[i]);
    }
    #pragma unroll
    for (int o = 16; o; o >>= 1) s += __shfl_down_sync(0xffffffff, s, o);
    if ((tid & 31) == 0) sdata[tid >> 5] = s;
    __syncthreads();
    if (tid < 32) {
        double v = sdata[tid];
        #pragma unroll
        for (int o = 16; o; o >>= 1) v += __shfl_down_sync(0xffffffff, v, o);
        if (tid == 0) out[0] = (float)(v / (double)(B_ * N_));
    }
}

extern "C" void kernel_launch(void* const* d_in, const int* in_sizes, int n_in,
                              void* d_out, int out_size) {
    const float* srcs = (const float*)d_in[0];
    const float* tgts = (const float*)d_in[1];
    float* out = (float*)d_out;

    cd_init_kernel<<<(B_ * N_ + 1023) / 1024, 1024>>>();
    dim3 grid(N_ / COLTILE, N_ / ROWTILE, B_);  // (4, 16, 8) = 512 blocks
    cd_main_kernel<<<grid, THREADS>>>(srcs, tgts);
    cd_reduce_kernel<<<1, 1024>>>(out);
}

// round 2
// speedup vs baseline: 1.8929x; 1.8929x over previous
#include <cuda_runtime.h>
#include <cstdint>

// Chamfer distance, B=8, D=3, N=4096, fp32.
// P[i,j] = |s_i|^2 + |t_j|^2 - 2 s_i . t_j ; loss = mean min_i P + mean min_j P
//
// R2 design: no redux, no atomics, no init kernel.
//  - lanes own 4 target columns (register colmin, packed fma.rn.f32x2)
//  - sources broadcast from SMEM, pre-duplicated pairs (no runtime packing)
//  - per-row row-min partial -> padded SMEM -> transpose reduce per 32 rows
//  - unique-writer global slices; two tiny reduce kernels finish the job.

#define NN 4096
#define BB 8
#define RT 512       // source rows per block tile
#define CT 512       // target cols per block tile (4 warps * 128)
#define NSLICE 32    // 8 coltiles * 4 warps
#define NPART 8      // rowtiles

__device__ float g_rowslice[NSLICE * BB * NN];  // [slice][b*N+row]
__device__ float g_colpart[NPART * BB * NN];    // [rowtile][b*N+col]
__device__ float g_bsum[128];

typedef unsigned long long u64;

__device__ __forceinline__ u64 pack2(float a, float b) {
    u64 r; asm("mov.b64 %0,{%1,%2};" : "=l"(r) : "f"(a), "f"(b)); return r;
}
__device__ __forceinline__ void unpack2(u64 v, float& a, float& b) {
    asm("mov.b64 {%0,%1},%2;" : "=f"(a), "=f"(b) : "l"(v));
}
__device__ __forceinline__ u64 add2(u64 a, u64 b) {
    u64 r; asm("add.rn.f32x2 %0,%1,%2;" : "=l"(r) : "l"(a), "l"(b)); return r;
}
__device__ __forceinline__ u64 fma2(u64 a, u64 b, u64 c) {
    u64 r; asm("fma.rn.f32x2 %0,%1,%2,%3;" : "=l"(r) : "l"(a), "l"(b), "l"(c)); return r;
}

__global__ __launch_bounds__(128) void cd_main_kernel(
    const float* __restrict__ srcs, const float* __restrict__ tgts) {
    __shared__ __align__(16) float smrow[RT * 8];       // 16 KB: per-row dup pairs
    __shared__ float spart[4][32 * 33];                  // 16.9 KB row-min partials

    const int b    = blockIdx.z;
    const int r0   = blockIdx.y * RT;
    const int c0   = blockIdx.x * CT;
    const int tid  = threadIdx.x;
    const int w    = tid >> 5;
    const int lane = tid & 31;

    // ---- stage source rows: (-2x,-2x,-2y,-2y) (-2z,-2z,|s|^2,|s|^2) ----
    const float* sb = srcs + (size_t)b * 3 * NN;
    for (int k = tid; k < RT; k += 128) {
        const int i = r0 + k;
        const float x = sb[i], y = sb[NN + i], z = sb[2 * NN + i];
        const float rs = x * x + y * y + z * z;
        float4* p = reinterpret_cast<float4*>(smrow + k * 8);
        p[0] = make_float4(-2.f * x, -2.f * x, -2.f * y, -2.f * y);
        p[1] = make_float4(-2.f * z, -2.f * z, rs, rs);
    }
    __syncthreads();

    // ---- per-lane targets: 4 consecutive columns, packed as 2 f32x2 pairs ----
    const int col0 = c0 + w * 128 + lane * 4;
    const float* tb = tgts + (size_t)b * 3 * NN;
    const float4 X = *reinterpret_cast<const float4*>(tb + col0);
    const float4 Y = *reinterpret_cast<const float4*>(tb + NN + col0);
    const float4 Z = *reinterpret_cast<const float4*>(tb + 2 * NN + col0);
    const u64 tx0 = pack2(X.x, X.y), tx1 = pack2(X.z, X.w);
    const u64 ty0 = pack2(Y.x, Y.y), ty1 = pack2(Y.z, Y.w);
    const u64 tz0 = pack2(Z.x, Z.y), tz1 = pack2(Z.z, Z.w);
    const u64 rt0 = pack2(X.x * X.x + Y.x * Y.x + Z.x * Z.x,
                          X.y * X.y + Y.y * Y.y + Z.y * Z.y);
    const u64 rt1 = pack2(X.z * X.z + Y.z * Y.z + Z.z * Z.z,
                          X.w * X.w + Y.w * Y.w + Z.w * Z.w);

    const float INF = __int_as_float(0x7F800000);
    float c0m = INF, c1m = INF, c2m = INF, c3m = INF;

    float* myPart = &spart[w][0];
    const int slice = blockIdx.x * 4 + w;
    float* rowOut = g_rowslice + (size_t)slice * (BB * NN) + b * NN + r0;

    for (int rc = 0; rc < RT; rc += 32) {
        const float* rp = smrow + rc * 8;
        #pragma unroll 4
        for (int r = 0; r < 32; ++r) {
            const ulonglong2 A  = *reinterpret_cast<const ulonglong2*>(rp + r * 8);
            const ulonglong2 Bq = *reinterpret_cast<const ulonglong2*>(rp + r * 8 + 4);
            u64 d0 = add2(Bq.y, rt0);
            d0 = fma2(A.x,  tx0, d0);
            d0 = fma2(A.y,  ty0, d0);
            d0 = fma2(Bq.x, tz0, d0);
            u64 d1 = add2(Bq.y, rt1);
            d1 = fma2(A.x,  tx1, d1);
            d1 = fma2(A.y,  ty1, d1);
            d1 = fma2(Bq.x, tz1, d1);
            float f0, f1, f2, f3;
            unpack2(d0, f0, f1); unpack2(d1, f2, f3);
            c0m = fminf(c0m, f0); c1m = fminf(c1m, f1);
            c2m = fminf(c2m, f2); c3m = fminf(c3m, f3);
            myPart[lane * 33 + r] = fminf(fminf(f0, f1), fminf(f2, f3));
        }
        __syncwarp();
        // transpose reduce: lane L reduces source row rc+L across the 32 lanes
        float m = myPart[lane];
        #pragma unroll
        for (int k = 1; k < 32; ++k) m = fminf(m, myPart[k * 33 + lane]);
        rowOut[rc + lane] = m;
        __syncwarp();
    }

    // column mins for this rowtile: unique writer, plain vector store
    *reinterpret_cast<float4*>(g_colpart + (size_t)blockIdx.y * (BB * NN) + b * NN + col0) =
        make_float4(c0m, c1m, c2m, c3m);
}

// combine slices/parts, produce per-block partial sums (128 blocks x 256 thr)
__global__ __launch_bounds__(256) void cd_reduce1_kernel() {
    __shared__ float swarp[8];
    const int g = blockIdx.x * 256 + threadIdx.x;  // 0..32767 = b*N+idx

    float v = g_rowslice[g];
    #pragma unroll
    for (int s = 1; s < NSLICE; ++s) v = fminf(v, g_rowslice[s * (BB * NN) + g]);
    float v2 = g_colpart[g];
    #pragma unroll
    for (int p = 1; p < NPART; ++p) v2 = fminf(v2, g_colpart[p * (BB * NN) + g]);

    float s = v + v2;
    #pragma unroll
    for (int o = 16; o; o >>= 1) s += __shfl_down_sync(0xffffffff, s, o);
    if ((threadIdx.x & 31) == 0) swarp[threadIdx.x >> 5] = s;
    __syncthreads();
    if (threadIdx.x < 32) {
        float t = (threadIdx.x < 8) ? swarp[threadIdx.x] : 0.f;
        #pragma unroll
        for (int o = 4; o; o >>= 1) t += __shfl_down_sync(0xffffffff, t, o);
        if (threadIdx.x == 0) g_bsum[blockIdx.x] = t;
    }
}

__global__ void cd_final_kernel(float* __restrict__ out) {
    __shared__ double swarp[4];
    const int tid = threadIdx.x;  // 128 threads
    double s = (double)g_bsum[tid];
    #pragma unroll
    for (int o = 16; o; o >>= 1) s += __shfl_down_sync(0xffffffff, s, o);
    if ((tid & 31) == 0) swarp[tid >> 5] = s;
    __syncthreads();
    if (tid < 32) {
        double t = (tid < 4) ? swarp[tid] : 0.0;
        #pragma unroll
        for (int o = 2; o; o >>= 1) t += __shfl_down_sync(0xffffffff, t, o);
        if (tid == 0) out[0] = (float)(t / (double)(BB * NN));
    }
}

extern "C" void kernel_launch(void* const* d_in, const int* in_sizes, int n_in,
                              void* d_out, int out_size) {
    const float* srcs = (const float*)d_in[0];
    const float* tgts = (const float*)d_in[1];
    float* out = (float*)d_out;

    dim3 grid(NN / CT, NN / RT, BB);  // (8, 8, 8) = 512 blocks
    cd_main_kernel<<<grid, 128>>>(srcs, tgts);
    cd_reduce1_kernel<<<128, 256>>>();
    cd_final_kernel<<<1, 128>>>(out);
}

// round 4
// speedup vs baseline: 2.1687x; 1.1457x over previous
#include <cuda_runtime.h>
#include <cstdint>

// Chamfer distance, B=8, D=3, N=4096, fp32.
// R4: R3 structure (8 cols/lane, RT=128, 1024 blocks) with scalar FMNMX mins
// (min.f32x2 not supported by this ptxas). No atomics/redux; unique-writer
// slices + 2 reduce kernels.

#define NN 4096
#define BB 8
#define RT 128        // source rows per block
#define CT 1024       // target cols per block = 4 warps * 256
#define NSLICE 16     // 4 coltiles * 4 warps
#define NPART 32      // rowtiles

__device__ float g_rowslice[NSLICE * BB * NN];
__device__ float g_colpart[NPART * BB * NN];
__device__ float g_bsum[128];

typedef unsigned long long u64;

__device__ __forceinline__ u64 pack2(float a, float b) {
    u64 r; asm("mov.b64 %0,{%1,%2};" : "=l"(r) : "f"(a), "f"(b)); return r;
}
__device__ __forceinline__ void unpack2(u64 v, float& a, float& b) {
    asm("mov.b64 {%0,%1},%2;" : "=f"(a), "=f"(b) : "l"(v));
}
__device__ __forceinline__ u64 add2(u64 a, u64 b) {
    u64 r; asm("add.rn.f32x2 %0,%1,%2;" : "=l"(r) : "l"(a), "l"(b)); return r;
}
__device__ __forceinline__ u64 fma2(u64 a, u64 b, u64 c) {
    u64 r; asm("fma.rn.f32x2 %0,%1,%2,%3;" : "=l"(r) : "l"(a), "l"(b), "l"(c)); return r;
}

__global__ __launch_bounds__(128) void cd_main_kernel(
    const float* __restrict__ srcs, const float* __restrict__ tgts) {
    __shared__ __align__(16) float smrow[RT * 8];   // 4 KB pre-dup source pairs
    __shared__ float spart[4][32 * 33];              // 16.9 KB row-min partials

    const int b    = blockIdx.z;
    const int r0   = blockIdx.y * RT;
    const int c0   = blockIdx.x * CT;
    const int tid  = threadIdx.x;
    const int w    = tid >> 5;
    const int lane = tid & 31;

    // stage source rows: (-2x,-2x,-2y,-2y)(-2z,-2z,rs,rs)
    const float* sb = srcs + (size_t)b * 3 * NN;
    {
        const int i = r0 + tid;
        const float x = sb[i], y = sb[NN + i], z = sb[2 * NN + i];
        const float rs = x * x + y * y + z * z;
        float4* p = reinterpret_cast<float4*>(smrow + tid * 8);
        p[0] = make_float4(-2.f * x, -2.f * x, -2.f * y, -2.f * y);
        p[1] = make_float4(-2.f * z, -2.f * z, rs, rs);
    }
    __syncthreads();

    // per-lane targets: 8 consecutive columns -> 4 f32x2 pairs per coordinate
    const int col0 = c0 + w * 256 + lane * 8;
    const float* tb = tgts + (size_t)b * 3 * NN;
    const float4 X0 = *reinterpret_cast<const float4*>(tb + col0);
    const float4 X1 = *reinterpret_cast<const float4*>(tb + col0 + 4);
    const float4 Y0 = *reinterpret_cast<const float4*>(tb + NN + col0);
    const float4 Y1 = *reinterpret_cast<const float4*>(tb + NN + col0 + 4);
    const float4 Z0 = *reinterpret_cast<const float4*>(tb + 2 * NN + col0);
    const float4 Z1 = *reinterpret_cast<const float4*>(tb + 2 * NN + col0 + 4);

    const u64 tx0 = pack2(X0.x, X0.y), tx1 = pack2(X0.z, X0.w);
    const u64 tx2 = pack2(X1.x, X1.y), tx3 = pack2(X1.z, X1.w);
    const u64 ty0 = pack2(Y0.x, Y0.y), ty1 = pack2(Y0.z, Y0.w);
    const u64 ty2 = pack2(Y1.x, Y1.y), ty3 = pack2(Y1.z, Y1.w);
    const u64 tz0 = pack2(Z0.x, Z0.y), tz1 = pack2(Z0.z, Z0.w);
    const u64 tz2 = pack2(Z1.x, Z1.y), tz3 = pack2(Z1.z, Z1.w);
    const u64 rt0 = pack2(X0.x*X0.x + Y0.x*Y0.x + Z0.x*Z0.x,
                          X0.y*X0.y + Y0.y*Y0.y + Z0.y*Z0.y);
    const u64 rt1 = pack2(X0.z*X0.z + Y0.z*Y0.z + Z0.z*Z0.z,
                          X0.w*X0.w + Y0.w*Y0.w + Z0.w*Z0.w);
    const u64 rt2 = pack2(X1.x*X1.x + Y1.x*Y1.x + Z1.x*Z1.x,
                          X1.y*X1.y + Y1.y*Y1.y + Z1.y*Z1.y);
    const u64 rt3 = pack2(X1.z*X1.z + Y1.z*Y1.z + Z1.z*Z1.z,
                          X1.w*X1.w + Y1.w*Y1.w + Z1.w*Z1.w);

    const float INF = __int_as_float(0x7F800000);
    float cm0 = INF, cm1 = INF, cm2 = INF, cm3 = INF;
    float cm4 = INF, cm5 = INF, cm6 = INF, cm7 = INF;

    float* myPart = &spart[w][0];
    const int slice = blockIdx.x * 4 + w;
    float* rowOut = g_rowslice + (size_t)slice * (BB * NN) + b * NN + r0;

    for (int rc = 0; rc < RT; rc += 32) {
        const float* rp = smrow + rc * 8;
        #pragma unroll 4
        for (int r = 0; r < 32; ++r) {
            const ulonglong2 A  = *reinterpret_cast<const ulonglong2*>(rp + r * 8);
            const ulonglong2 Bq = *reinterpret_cast<const ulonglong2*>(rp + r * 8 + 4);
            u64 d0 = add2(Bq.y, rt0);
            u64 d1 = add2(Bq.y, rt1);
            u64 d2 = add2(Bq.y, rt2);
            u64 d3 = add2(Bq.y, rt3);
            d0 = fma2(A.x, tx0, d0);  d1 = fma2(A.x, tx1, d1);
            d2 = fma2(A.x, tx2, d2);  d3 = fma2(A.x, tx3, d3);
            d0 = fma2(A.y, ty0, d0);  d1 = fma2(A.y, ty1, d1);
            d2 = fma2(A.y, ty2, d2);  d3 = fma2(A.y, ty3, d3);
            d0 = fma2(Bq.x, tz0, d0); d1 = fma2(Bq.x, tz1, d1);
            d2 = fma2(Bq.x, tz2, d2); d3 = fma2(Bq.x, tz3, d3);
            float f0, f1, f2, f3, f4, f5, f6, f7;
            unpack2(d0, f0, f1); unpack2(d1, f2, f3);
            unpack2(d2, f4, f5); unpack2(d3, f6, f7);
            cm0 = fminf(cm0, f0); cm1 = fminf(cm1, f1);
            cm2 = fminf(cm2, f2); cm3 = fminf(cm3, f3);
            cm4 = fminf(cm4, f4); cm5 = fminf(cm5, f5);
            cm6 = fminf(cm6, f6); cm7 = fminf(cm7, f7);
            const float p01 = fminf(f0, f1), p23 = fminf(f2, f3);
            const float p45 = fminf(f4, f5), p67 = fminf(f6, f7);
            myPart[lane * 33 + r] = fminf(fminf(p01, p23), fminf(p45, p67));
        }
        __syncwarp();
        // transpose reduce: lane L reduces source row rc+L across 32 lanes
        float m = myPart[lane];
        #pragma unroll
        for (int k = 1; k < 32; ++k) m = fminf(m, myPart[k * 33 + lane]);
        rowOut[rc + lane] = m;
        __syncwarp();
    }

    // column mins for this rowtile (unique writer)
    float* cp = g_colpart + (size_t)blockIdx.y * (BB * NN) + b * NN + col0;
    *reinterpret_cast<float4*>(cp)     = make_float4(cm0, cm1, cm2, cm3);
    *reinterpret_cast<float4*>(cp + 4) = make_float4(cm4, cm5, cm6, cm7);
}

__global__ __launch_bounds__(256) void cd_reduce1_kernel() {
    __shared__ float swarp[8];
    const int g = blockIdx.x * 256 + threadIdx.x;  // 0..32767

    float v = g_rowslice[g];
    #pragma unroll
    for (int s = 1; s < NSLICE; ++s) v = fminf(v, g_rowslice[s * (BB * NN) + g]);
    float v2 = g_colpart[g];
    #pragma unroll
    for (int p = 1; p < NPART; ++p) v2 = fminf(v2, g_colpart[p * (BB * NN) + g]);

    float s = v + v2;
    #pragma unroll
    for (int o = 16; o; o >>= 1) s += __shfl_down_sync(0xffffffff, s, o);
    if ((threadIdx.x & 31) == 0) swarp[threadIdx.x >> 5] = s;
    __syncthreads();
    if (threadIdx.x < 32) {
        float t = (threadIdx.x < 8) ? swarp[threadIdx.x] : 0.f;
        #pragma unroll
        for (int o = 4; o; o >>= 1) t += __shfl_down_sync(0xffffffff, t, o);
        if (threadIdx.x == 0) g_bsum[blockIdx.x] = t;
    }
}

__global__ void cd_final_kernel(float* __restrict__ out) {
    __shared__ double swarp[4];
    const int tid = threadIdx.x;  // 128
    double s = (double)g_bsum[tid];
    #pragma unroll
    for (int o = 16; o; o >>= 1) s += __shfl_down_sync(0xffffffff, s, o);
    if ((tid & 31) == 0) swarp[tid >> 5] = s;
    __syncthreads();
    if (tid < 32) {
        double t = (tid < 4) ? swarp[tid] : 0.0;
        #pragma unroll
        for (int o = 2; o; o >>= 1) t += __shfl_down_sync(0xffffffff, t, o);
        if (tid == 0) out[0] = (float)(t / (double)(BB * NN));
    }
}

extern "C" void kernel_launch(void* const* d_in, const int* in_sizes, int n_in,
                              void* d_out, int out_size) {
    const float* srcs = (const float*)d_in[0];
    const float* tgts = (const float*)d_in[1];
    float* out = (float*)d_out;

    dim3 grid(NN / CT, NN / RT, BB);  // (4, 32, 8) = 1024 blocks
    cd_main_kernel<<<grid, 128>>>(srcs, tgts);
    cd_reduce1_kernel<<<128, 256>>>();
    cd_final_kernel<<<1, 128>>>(out);
}

// round 5
// speedup vs baseline: 2.2955x; 1.0584x over previous
#include <cuda_runtime.h>
#include <cstdint>

// Chamfer distance, B=8, D=3, N=4096, fp32.
// R5: R4 + manual software pipelining of the SMEM row loads (padded row),
// independent add2 heads for ILP, reg cap for 7 resident blocks/SM,
// split transpose-reduce chain. No atomics/redux.

#define NN 4096
#define BB 8
#define RT 128        // source rows per block
#define CT 1024       // target cols per block = 4 warps * 256
#define NSLICE 16     // 4 coltiles * 4 warps
#define NPART 32      // rowtiles

__device__ float g_rowslice[NSLICE * BB * NN];
__device__ float g_colpart[NPART * BB * NN];
__device__ float g_bsum[128];

typedef unsigned long long u64;

__device__ __forceinline__ u64 pack2(float a, float b) {
    u64 r; asm("mov.b64 %0,{%1,%2};" : "=l"(r) : "f"(a), "f"(b)); return r;
}
__device__ __forceinline__ void unpack2(u64 v, float& a, float& b) {
    asm("mov.b64 {%0,%1},%2;" : "=f"(a), "=f"(b) : "l"(v));
}
__device__ __forceinline__ u64 add2(u64 a, u64 b) {
    u64 r; asm("add.rn.f32x2 %0,%1,%2;" : "=l"(r) : "l"(a), "l"(b)); return r;
}
__device__ __forceinline__ u64 fma2(u64 a, u64 b, u64 c) {
    u64 r; asm("fma.rn.f32x2 %0,%1,%2,%3;" : "=l"(r) : "l"(a), "l"(b), "l"(c)); return r;
}

__global__ __launch_bounds__(128, 7) void cd_main_kernel(
    const float* __restrict__ srcs, const float* __restrict__ tgts) {
    __shared__ __align__(16) float smrow[(RT + 1) * 8];  // +1 pad row for prefetch
    __shared__ float spart[4][32 * 33];                   // row-min partials

    const int b    = blockIdx.z;
    const int r0   = blockIdx.y * RT;
    const int c0   = blockIdx.x * CT;
    const int tid  = threadIdx.x;
    const int w    = tid >> 5;
    const int lane = tid & 31;

    // stage source rows: (-2x,-2x,-2y,-2y)(-2z,-2z,rs,rs); pad row = zeros
    const float* sb = srcs + (size_t)b * 3 * NN;
    {
        const int i = r0 + tid;
        const float x = sb[i], y = sb[NN + i], z = sb[2 * NN + i];
        const float rs = x * x + y * y + z * z;
        float4* p = reinterpret_cast<float4*>(smrow + tid * 8);
        p[0] = make_float4(-2.f * x, -2.f * x, -2.f * y, -2.f * y);
        p[1] = make_float4(-2.f * z, -2.f * z, rs, rs);
        if (tid < 8) smrow[RT * 8 + tid] = 0.f;
    }
    __syncthreads();

    // per-lane targets: 8 consecutive columns -> 4 f32x2 pairs per coordinate
    const int col0 = c0 + w * 256 + lane * 8;
    const float* tb = tgts + (size_t)b * 3 * NN;
    const float4 X0 = *reinterpret_cast<const float4*>(tb + col0);
    const float4 X1 = *reinterpret_cast<const float4*>(tb + col0 + 4);
    const float4 Y0 = *reinterpret_cast<const float4*>(tb + NN + col0);
    const float4 Y1 = *reinterpret_cast<const float4*>(tb + NN + col0 + 4);
    const float4 Z0 = *reinterpret_cast<const float4*>(tb + 2 * NN + col0);
    const float4 Z1 = *reinterpret_cast<const float4*>(tb + 2 * NN + col0 + 4);

    const u64 tx0 = pack2(X0.x, X0.y), tx1 = pack2(X0.z, X0.w);
    const u64 tx2 = pack2(X1.x, X1.y), tx3 = pack2(X1.z, X1.w);
    const u64 ty0 = pack2(Y0.x, Y0.y), ty1 = pack2(Y0.z, Y0.w);
    const u64 ty2 = pack2(Y1.x, Y1.y), ty3 = pack2(Y1.z, Y1.w);
    const u64 tz0 = pack2(Z0.x, Z0.y), tz1 = pack2(Z0.z, Z0.w);
    const u64 tz2 = pack2(Z1.x, Z1.y), tz3 = pack2(Z1.z, Z1.w);
    const u64 rt0 = pack2(X0.x*X0.x + Y0.x*Y0.x + Z0.x*Z0.x,
                          X0.y*X0.y + Y0.y*Y0.y + Z0.y*Z0.y);
    const u64 rt1 = pack2(X0.z*X0.z + Y0.z*Y0.z + Z0.z*Z0.z,
                          X0.w*X0.w + Y0.w*Y0.w + Z0.w*Z0.w);
    const u64 rt2 = pack2(X1.x*X1.x + Y1.x*Y1.x + Z1.x*Z1.x,
                          X1.y*X1.y + Y1.y*Y1.y + Z1.y*Z1.y);
    const u64 rt3 = pack2(X1.z*X1.z + Y1.z*Y1.z + Z1.z*Z1.z,
                          X1.w*X1.w + Y1.w*Y1.w + Z1.w*Z1.w);

    const float INF = __int_as_float(0x7F800000);
    float cm0 = INF, cm1 = INF, cm2 = INF, cm3 = INF;
    float cm4 = INF, cm5 = INF, cm6 = INF, cm7 = INF;

    float* myPart = &spart[w][0];
    const int slice = blockIdx.x * 4 + w;
    float* rowOut = g_rowslice + (size_t)slice * (BB * NN) + b * NN + r0;

    // software-pipelined over rows: A/Bq hold row r, prefetch row r+1
    ulonglong2 A  = *reinterpret_cast<const ulonglong2*>(smrow);
    ulonglong2 Bq = *reinterpret_cast<const ulonglong2*>(smrow + 4);

    for (int rc = 0; rc < RT; rc += 32) {
        #pragma unroll 8
        for (int rr = 0; rr < 32; ++rr) {
            const int r = rc + rr;
            const float* np = smrow + (r + 1) * 8;
            const ulonglong2 An = *reinterpret_cast<const ulonglong2*>(np);
            const ulonglong2 Bn = *reinterpret_cast<const ulonglong2*>(np + 4);

            // independent heads, then 3-deep fma chains (ILP = 4)
            u64 d0 = add2(Bq.y, rt0);
            u64 d1 = add2(Bq.y, rt1);
            u64 d2 = add2(Bq.y, rt2);
            u64 d3 = add2(Bq.y, rt3);
            d0 = fma2(A.x, tx0, d0);  d1 = fma2(A.x, tx1, d1);
            d2 = fma2(A.x, tx2, d2);  d3 = fma2(A.x, tx3, d3);
            d0 = fma2(A.y, ty0, d0);  d1 = fma2(A.y, ty1, d1);
            d2 = fma2(A.y, ty2, d2);  d3 = fma2(A.y, ty3, d3);
            d0 = fma2(Bq.x, tz0, d0); d1 = fma2(Bq.x, tz1, d1);
            d2 = fma2(Bq.x, tz2, d2); d3 = fma2(Bq.x, tz3, d3);

            float f0, f1, f2, f3, f4, f5, f6, f7;
            unpack2(d0, f0, f1); unpack2(d1, f2, f3);
            unpack2(d2, f4, f5); unpack2(d3, f6, f7);
            cm0 = fminf(cm0, f0); cm1 = fminf(cm1, f1);
            cm2 = fminf(cm2, f2); cm3 = fminf(cm3, f3);
            cm4 = fminf(cm4, f4); cm5 = fminf(cm5, f5);
            cm6 = fminf(cm6, f6); cm7 = fminf(cm7, f7);
            const float p01 = fminf(f0, f1), p23 = fminf(f2, f3);
            const float p45 = fminf(f4, f5), p67 = fminf(f6, f7);
            myPart[lane * 33 + rr] = fminf(fminf(p01, p23), fminf(p45, p67));

            A = An; Bq = Bn;
        }
        __syncwarp();
        // transpose reduce with two accumulator chains
        float ma = myPart[lane];
        float mb = myPart[16 * 33 + lane];
        #pragma unroll
        for (int k = 1; k < 16; ++k) {
            ma = fminf(ma, myPart[k * 33 + lane]);
            mb = fminf(mb, myPart[(k + 16) * 33 + lane]);
        }
        rowOut[rc + lane] = fminf(ma, mb);
        __syncwarp();
    }

    // column mins for this rowtile (unique writer)
    float* cp = g_colpart + (size_t)blockIdx.y * (BB * NN) + b * NN + col0;
    *reinterpret_cast<float4*>(cp)     = make_float4(cm0, cm1, cm2, cm3);
    *reinterpret_cast<float4*>(cp + 4) = make_float4(cm4, cm5, cm6, cm7);
}

__global__ __launch_bounds__(256) void cd_reduce1_kernel() {
    __shared__ float swarp[8];
    const int g = blockIdx.x * 256 + threadIdx.x;  // 0..32767

    float v = g_rowslice[g];
    #pragma unroll
    for (int s = 1; s < NSLICE; ++s) v = fminf(v, g_rowslice[s * (BB * NN) + g]);
    float v2 = g_colpart[g];
    #pragma unroll
    for (int p = 1; p < NPART; ++p) v2 = fminf(v2, g_colpart[p * (BB * NN) + g]);

    float s = v + v2;
    #pragma unroll
    for (int o = 16; o; o >>= 1) s += __shfl_down_sync(0xffffffff, s, o);
    if ((threadIdx.x & 31) == 0) swarp[threadIdx.x >> 5] = s;
    __syncthreads();
    if (threadIdx.x < 32) {
        float t = (threadIdx.x < 8) ? swarp[threadIdx.x] : 0.f;
        #pragma unroll
        for (int o = 4; o; o >>= 1) t += __shfl_down_sync(0xffffffff, t, o);
        if (threadIdx.x == 0) g_bsum[blockIdx.x] = t;
    }
}

__global__ void cd_final_kernel(float* __restrict__ out) {
    __shared__ double swarp[4];
    const int tid = threadIdx.x;  // 128
    double s = (double)g_bsum[tid];
    #pragma unroll
    for (int o = 16; o; o >>= 1) s += __shfl_down_sync(0xffffffff, s, o);
    if ((tid & 31) == 0) swarp[tid >> 5] = s;
    __syncthreads();
    if (tid < 32) {
        double t = (tid < 4) ? swarp[tid] : 0.0;
        #pragma unroll
        for (int o = 2; o; o >>= 1) t += __shfl_down_sync(0xffffffff, t, o);
        if (tid == 0) out[0] = (float)(t / (double)(BB * NN));
    }
}

extern "C" void kernel_launch(void* const* d_in, const int* in_sizes, int n_in,
                              void* d_out, int out_size) {
    const float* srcs = (const float*)d_in[0];
    const float* tgts = (const float*)d_in[1];
    float* out = (float*)d_out;

    dim3 grid(NN / CT, NN / RT, BB);  // (4, 32, 8) = 1024 blocks
    cd_main_kernel<<<grid, 128>>>(srcs, tgts);
    cd_reduce1_kernel<<<128, 256>>>();
    cd_final_kernel<<<1, 128>>>(out);
}

// round 6
// speedup vs baseline: 2.2973x; 1.0008x over previous
#include <cuda_runtime.h>
#include <cstdint>

// Chamfer distance, B=8, D=3, N=4096, fp32.
// R6: break fma/alu phase-lock by lagging the min stage one row behind the
// distance computation (independent op sets -> ptxas interleaves pipes).
// Computes h = d/2 (head add2(hrs,hrt)) to save registers; x2 fixup in reduce1.

#define NN 4096
#define BB 8
#define RT 128        // source rows per block
#define CT 1024       // target cols per block = 4 warps * 256
#define NSLICE 16     // 4 coltiles * 4 warps
#define NPART 32      // rowtiles

__device__ float g_rowslice[NSLICE * BB * NN];
__device__ float g_colpart[NPART * BB * NN];
__device__ float g_bsum[128];

typedef unsigned long long u64;

__device__ __forceinline__ u64 pack2(float a, float b) {
    u64 r; asm("mov.b64 %0,{%1,%2};" : "=l"(r) : "f"(a), "f"(b)); return r;
}
__device__ __forceinline__ void unpack2(u64 v, float& a, float& b) {
    asm("mov.b64 {%0,%1},%2;" : "=f"(a), "=f"(b) : "l"(v));
}
__device__ __forceinline__ u64 add2(u64 a, u64 b) {
    u64 r; asm("add.rn.f32x2 %0,%1,%2;" : "=l"(r) : "l"(a), "l"(b)); return r;
}
__device__ __forceinline__ u64 fma2(u64 a, u64 b, u64 c) {
    u64 r; asm("fma.rn.f32x2 %0,%1,%2,%3;" : "=l"(r) : "l"(a), "l"(b), "l"(c)); return r;
}

struct Quad { u64 d0, d1, d2, d3; };

__global__ __launch_bounds__(128, 7) void cd_main_kernel(
    const float* __restrict__ srcs, const float* __restrict__ tgts) {
    __shared__ __align__(16) float smrow[RT * 8];   // (-x,-x,-y,-y)(-z,-z,hrs,hrs)
    __shared__ float spart[4][32 * 33];              // row-min partials

    const int b    = blockIdx.z;
    const int r0   = blockIdx.y * RT;
    const int c0   = blockIdx.x * CT;
    const int tid  = threadIdx.x;
    const int w    = tid >> 5;
    const int lane = tid & 31;

    // stage source rows: negated coords + half-norm (h = d/2 formulation)
    const float* sb = srcs + (size_t)b * 3 * NN;
    {
        const int i = r0 + tid;
        const float x = sb[i], y = sb[NN + i], z = sb[2 * NN + i];
        const float hrs = 0.5f * (x * x + y * y + z * z);
        float4* p = reinterpret_cast<float4*>(smrow + tid * 8);
        p[0] = make_float4(-x, -x, -y, -y);
        p[1] = make_float4(-z, -z, hrs, hrs);
    }
    __syncthreads();

    // per-lane targets: 8 consecutive columns -> pairs; hrt = |t|^2/2
    const int col0 = c0 + w * 256 + lane * 8;
    const float* tb = tgts + (size_t)b * 3 * NN;
    const float4 X0 = *reinterpret_cast<const float4*>(tb + col0);
    const float4 X1 = *reinterpret_cast<const float4*>(tb + col0 + 4);
    const float4 Y0 = *reinterpret_cast<const float4*>(tb + NN + col0);
    const float4 Y1 = *reinterpret_cast<const float4*>(tb + NN + col0 + 4);
    const float4 Z0 = *reinterpret_cast<const float4*>(tb + 2 * NN + col0);
    const float4 Z1 = *reinterpret_cast<const float4*>(tb + 2 * NN + col0 + 4);

    const u64 tx0 = pack2(X0.x, X0.y), tx1 = pack2(X0.z, X0.w);
    const u64 tx2 = pack2(X1.x, X1.y), tx3 = pack2(X1.z, X1.w);
    const u64 ty0 = pack2(Y0.x, Y0.y), ty1 = pack2(Y0.z, Y0.w);
    const u64 ty2 = pack2(Y1.x, Y1.y), ty3 = pack2(Y1.z, Y1.w);
    const u64 tz0 = pack2(Z0.x, Z0.y), tz1 = pack2(Z0.z, Z0.w);
    const u64 tz2 = pack2(Z1.x, Z1.y), tz3 = pack2(Z1.z, Z1.w);
    const u64 hrt0 = pack2(0.5f*(X0.x*X0.x + Y0.x*Y0.x + Z0.x*Z0.x),
                           0.5f*(X0.y*X0.y + Y0.y*Y0.y + Z0.y*Z0.y));
    const u64 hrt1 = pack2(0.5f*(X0.z*X0.z + Y0.z*Y0.z + Z0.z*Z0.z),
                           0.5f*(X0.w*X0.w + Y0.w*Y0.w + Z0.w*Z0.w));
    const u64 hrt2 = pack2(0.5f*(X1.x*X1.x + Y1.x*Y1.x + Z1.x*Z1.x),
                           0.5f*(X1.y*X1.y + Y1.y*Y1.y + Z1.y*Z1.y));
    const u64 hrt3 = pack2(0.5f*(X1.z*X1.z + Y1.z*Y1.z + Z1.z*Z1.z),
                           0.5f*(X1.w*X1.w + Y1.w*Y1.w + Z1.w*Z1.w));

    const float INF = __int_as_float(0x7F800000);
    float cm0 = INF, cm1 = INF, cm2 = INF, cm3 = INF;
    float cm4 = INF, cm5 = INF, cm6 = INF, cm7 = INF;

    float* myPart = &spart[w][0];
    const int slice = blockIdx.x * 4 + w;
    float* rowOut = g_rowslice + (size_t)slice * (BB * NN) + b * NN + r0;

    // distance for one staged row (2 LDS.128 + 4 add2 + 12 fma2)
    auto computeRow = [&](int r) -> Quad {
        const float* rp = smrow + r * 8;
        const ulonglong2 A  = *reinterpret_cast<const ulonglong2*>(rp);
        const ulonglong2 Bq = *reinterpret_cast<const ulonglong2*>(rp + 4);
        Quad q;
        q.d0 = add2(Bq.y, hrt0);
        q.d1 = add2(Bq.y, hrt1);
        q.d2 = add2(Bq.y, hrt2);
        q.d3 = add2(Bq.y, hrt3);
        q.d0 = fma2(A.x, tx0, q.d0);  q.d1 = fma2(A.x, tx1, q.d1);
        q.d2 = fma2(A.x, tx2, q.d2);  q.d3 = fma2(A.x, tx3, q.d3);
        q.d0 = fma2(A.y, ty0, q.d0);  q.d1 = fma2(A.y, ty1, q.d1);
        q.d2 = fma2(A.y, ty2, q.d2);  q.d3 = fma2(A.y, ty3, q.d3);
        q.d0 = fma2(Bq.x, tz0, q.d0); q.d1 = fma2(Bq.x, tz1, q.d1);
        q.d2 = fma2(Bq.x, tz2, q.d2); q.d3 = fma2(Bq.x, tz3, q.d3);
        return q;
    };
    // min stage for a lagged row (8 col-min FMNMX + 7 tree FMNMX + STS)
    auto minsRow = [&](const Quad& q, int slot) {
        float f0, f1, f2, f3, f4, f5, f6, f7;
        unpack2(q.d0, f0, f1); unpack2(q.d1, f2, f3);
        unpack2(q.d2, f4, f5); unpack2(q.d3, f6, f7);
        cm0 = fminf(cm0, f0); cm1 = fminf(cm1, f1);
        cm2 = fminf(cm2, f2); cm3 = fminf(cm3, f3);
        cm4 = fminf(cm4, f4); cm5 = fminf(cm5, f5);
        cm6 = fminf(cm6, f6); cm7 = fminf(cm7, f7);
        const float p01 = fminf(f0, f1), p23 = fminf(f2, f3);
        const float p45 = fminf(f4, f5), p67 = fminf(f6, f7);
        myPart[lane * 33 + slot] = fminf(fminf(p01, p23), fminf(p45, p67));
    };

    for (int rc = 0; rc < RT; rc += 32) {
        Quad prev = computeRow(rc);          // peel row 0 of chunk
        #pragma unroll 4
        for (int rr = 0; rr < 31; ++rr) {    // fma(row rr+1) interleaves mins(row rr)
            Quad cur = computeRow(rc + rr + 1);
            minsRow(prev, rr);
            prev = cur;
        }
        minsRow(prev, 31);                   // flush row 31
        __syncwarp();
        // transpose reduce with two accumulator chains
        float ma = myPart[lane];
        float mb = myPart[16 * 33 + lane];
        #pragma unroll
        for (int k = 1; k < 16; ++k) {
            ma = fminf(ma, myPart[k * 33 + lane]);
            mb = fminf(mb, myPart[(k + 16) * 33 + lane]);
        }
        rowOut[rc + lane] = fminf(ma, mb);
        __syncwarp();
    }

    // column mins (h-scale; x2 applied in reduce1), unique writer
    float* cp = g_colpart + (size_t)blockIdx.y * (BB * NN) + b * NN + col0;
    *reinterpret_cast<float4*>(cp)     = make_float4(cm0, cm1, cm2, cm3);
    *reinterpret_cast<float4*>(cp + 4) = make_float4(cm4, cm5, cm6, cm7);
}

__global__ __launch_bounds__(256) void cd_reduce1_kernel() {
    __shared__ float swarp[8];
    const int g = blockIdx.x * 256 + threadIdx.x;  // 0..32767

    float v = g_rowslice[g];
    #pragma unroll
    for (int s = 1; s < NSLICE; ++s) v = fminf(v, g_rowslice[s * (BB * NN) + g]);
    float v2 = g_colpart[g];
    #pragma unroll
    for (int p = 1; p < NPART; ++p) v2 = fminf(v2, g_colpart[p * (BB * NN) + g]);

    float s = 2.0f * (v + v2);   // undo h = d/2 scaling
    #pragma unroll
    for (int o = 16; o; o >>= 1) s += __shfl_down_sync(0xffffffff, s, o);
    if ((threadIdx.x & 31) == 0) swarp[threadIdx.x >> 5] = s;
    __syncthreads();
    if (threadIdx.x < 32) {
        float t = (threadIdx.x < 8) ? swarp[threadIdx.x] : 0.f;
        #pragma unroll
        for (int o = 4; o; o >>= 1) t += __shfl_down_sync(0xffffffff, t, o);
        if (threadIdx.x == 0) g_bsum[blockIdx.x] = t;
    }
}

__global__ void cd_final_kernel(float* __restrict__ out) {
    __shared__ double swarp[4];
    const int tid = threadIdx.x;  // 128
    double s = (double)g_bsum[tid];
    #pragma unroll
    for (int o = 16; o; o >>= 1) s += __shfl_down_sync(0xffffffff, s, o);
    if ((tid & 31) == 0) swarp[tid >> 5] = s;
    __syncthreads();
    if (tid < 32) {
        double t = (tid < 4) ? swarp[tid] : 0.0;
        #pragma unroll
        for (int o = 2; o; o >>= 1) t += __shfl_down_sync(0xffffffff, t, o);
        if (tid == 0) out[0] = (float)(t / (double)(BB * NN));
    }
}

extern "C" void kernel_launch(void* const* d_in, const int* in_sizes, int n_in,
                              void* d_out, int out_size) {
    const float* srcs = (const float*)d_in[0];
    const float* tgts = (const float*)d_in[1];
    float* out = (float*)d_out;

    dim3 grid(NN / CT, NN / RT, BB);  // (4, 32, 8) = 1024 blocks
    cd_main_kernel<<<grid, 128>>>(srcs, tgts);
    cd_reduce1_kernel<<<128, 256>>>();
    cd_final_kernel<<<1, 128>>>(out);
}